// round 2
// baseline (speedup 1.0000x reference)
#include <cuda_runtime.h>
#include <math.h>

#define BB 4
#define HH 8
#define LL 1024
#define DIMF 256
#define DH 32
#define SCL 0.0625f
#define NEGB (-1e30f)

__device__ float g_xq[BB*HH*LL*DH];
__device__ float g_rk[BB*HH*LL*DH];
__device__ float g_xv[BB*HH*LL*DH];
__device__ float g_rv[BB*HH*LL*DH];
__device__ float g_q [BB*HH*LL*DH];
__device__ float g_k [BB*HH*LL*DH];
__device__ float g_S [(size_t)BB*HH*LL*LL];
__device__ float g_rm[BB*HH*LL];
__device__ float g_rs[BB*HH*LL];
__device__ float g_cs[BB*HH*LL];
__device__ float g_v [BB*LL*DIMF];
__device__ float g_vr[BB*LL*DIMF];

/* K1: per-head projections xq=xh@Wq, xv=xh@Wv, rk=rxh@Wk, rv=rxh@Wv; zero g_cs */
__global__ void k1_proj(const float* __restrict__ x, const float* __restrict__ rx,
                        const float* __restrict__ Wq, const float* __restrict__ Wk,
                        const float* __restrict__ Wv) {
    __shared__ float wq[DH*DH], wk[DH*DH], wv[DH*DH];
    __shared__ float xr[DIMF], rr[DIMF];
    int tid = threadIdx.x, bl = blockIdx.x;
    if (bl < 128) g_cs[bl*256 + tid] = 0.f;
    for (int i = tid; i < DH*DH; i += 256) { wq[i]=Wq[i]; wk[i]=Wk[i]; wv[i]=Wv[i]; }
    xr[tid] = x[(size_t)bl*DIMF + tid];
    rr[tid] = rx[(size_t)bl*DIMF + tid];
    __syncthreads();
    int h = tid>>5, d = tid&31;
    float aq=0.f, av=0.f, ak=0.f, ar=0.f;
#pragma unroll
    for (int j=0;j<DH;j++) {
        float xv_ = xr[h*DH+j], rv_ = rr[h*DH+j];
        aq += xv_*wq[j*DH+d]; av += xv_*wv[j*DH+d];
        ak += rv_*wk[j*DH+d]; ar += rv_*wv[j*DH+d];
    }
    int b = bl>>10, l = bl&1023;
    size_t o = (((size_t)b*HH + h)*LL + l)*DH + d;
    g_xq[o]=aq; g_xv[o]=av; g_rk[o]=ak; g_rv[o]=ar;
}

/* K2: q = adj @ xq (z=0), k = adj_resize @ rk (z=1). 128x32 tile, 4x4 regs. */
__global__ void k2_agg(const float* __restrict__ adj, const float* __restrict__ adjr) {
    __shared__ float aS[128][36];
    __shared__ float xS[32][36];
    int tid = threadIdx.x, bh = blockIdx.y;
    int r0 = blockIdx.x * 128;
    const float* A = blockIdx.z ? adjr : adj;
    const float* X = blockIdx.z ? g_rk : g_xq;
    float*       O = blockIdx.z ? g_k  : g_q;
    int rg = tid>>3, cg = tid&7;
    float4 acc[4];
#pragma unroll
    for (int i=0;i<4;i++) acc[i] = make_float4(0.f,0.f,0.f,0.f);
    const float* Ab = A + (size_t)bh*LL*LL;
    for (int t0=0; t0<LL; t0+=32) {
#pragma unroll
        for (int i=0;i<4;i++) {
            int e = tid + i*256, r = e>>3, c4 = (e&7)*4;
            *(float4*)&aS[r][c4] = *(const float4*)(Ab + (size_t)(r0+r)*LL + t0 + c4);
        }
        {
            int tt = tid>>3, d4 = (tid&7)*4;
            *(float4*)&xS[tt][d4] = *(const float4*)(X + ((size_t)bh*LL + t0+tt)*DH + d4);
        }
        __syncthreads();
#pragma unroll
        for (int tq=0; tq<8; tq++) {
            float4 a4[4], x4[4];
#pragma unroll
            for (int i=0;i<4;i++) a4[i] = *(const float4*)&aS[rg+32*i][tq*4];
#pragma unroll
            for (int m=0;m<4;m++) x4[m] = *(const float4*)&xS[tq*4+m][cg*4];
#pragma unroll
            for (int i=0;i<4;i++) {
                acc[i].x += a4[i].x*x4[0].x + a4[i].y*x4[1].x + a4[i].z*x4[2].x + a4[i].w*x4[3].x;
                acc[i].y += a4[i].x*x4[0].y + a4[i].y*x4[1].y + a4[i].z*x4[2].y + a4[i].w*x4[3].y;
                acc[i].z += a4[i].x*x4[0].z + a4[i].y*x4[1].z + a4[i].z*x4[2].z + a4[i].w*x4[3].z;
                acc[i].w += a4[i].x*x4[0].w + a4[i].y*x4[1].w + a4[i].z*x4[2].w + a4[i].w*x4[3].w;
            }
        }
        __syncthreads();
    }
#pragma unroll
    for (int i=0;i<4;i++)
        *(float4*)(O + ((size_t)bh*LL + r0+rg+32*i)*DH + cg*4) = acc[i];
}

/* K3: S = leaky(scale * q k^T), per (b,h). 64x64 tile, K=32 full. */
__global__ void k3_logits() {
    __shared__ float qs[64][36], ks[64][36];
    int tid = threadIdx.x, bh = blockIdx.y;
    int l0 = (blockIdx.x & 15)*64, t0 = (blockIdx.x >> 4)*64;
#pragma unroll
    for (int i=0;i<2;i++) {
        int e = tid + i*256, r = e>>3, d4 = (e&7)*4;
        *(float4*)&qs[r][d4] = *(const float4*)(g_q + ((size_t)bh*LL + l0+r)*DH + d4);
        *(float4*)&ks[r][d4] = *(const float4*)(g_k + ((size_t)bh*LL + t0+r)*DH + d4);
    }
    __syncthreads();
    int rg = tid>>4, cg = tid&15;
    float acc[4][4];
#pragma unroll
    for (int i=0;i<4;i++)
#pragma unroll
        for (int j=0;j<4;j++) acc[i][j]=0.f;
#pragma unroll
    for (int dq=0; dq<8; dq++) {
        float4 q4[4], k4[4];
#pragma unroll
        for (int i=0;i<4;i++) q4[i] = *(const float4*)&qs[rg+16*i][dq*4];
#pragma unroll
        for (int j=0;j<4;j++) k4[j] = *(const float4*)&ks[cg*4+j][dq*4];
#pragma unroll
        for (int i=0;i<4;i++)
#pragma unroll
            for (int j=0;j<4;j++)
                acc[i][j] += q4[i].x*k4[j].x + q4[i].y*k4[j].y
                           + q4[i].z*k4[j].z + q4[i].w*k4[j].w;
    }
#pragma unroll
    for (int i=0;i<4;i++) {
        float4 o; float* p = (float*)&o;
#pragma unroll
        for (int j=0;j<4;j++){ float v = acc[i][j]*SCL; p[j] = v>0.f ? v : 0.01f*v; }
        *(float4*)(g_S + (size_t)bh*LL*LL + (size_t)(l0+rg+16*i)*LL + t0 + cg*4) = o;
    }
}

/* K4: R-mix across heads, mask by adj, write masked logits to A-buffer,
   online per-row softmax stats (per-lane running max/sum, shfl merge). */
__global__ void k4_mix(const float* __restrict__ adj, const float* __restrict__ R,
                       float* __restrict__ Ab) {
    __shared__ float Ssm[8*16*32];
    int tid = threadIdx.x, b = blockIdx.y;
    int l0 = blockIdx.x * 16;
    int i = tid>>5, lane = tid&31;
    float Rr[8];
#pragma unroll
    for (int h=0;h<8;h++) Rr[h] = R[i*8+h];
    float m16[16], s16[16];
#pragma unroll
    for (int l=0;l<16;l++){ m16[l]=NEGB; s16[l]=0.f; }
    for (int t0=0; t0<LL; t0+=32) {
        __syncthreads();
#pragma unroll
        for (int it=0; it<4; it++) {
            int e = tid + it*256;
            int h = e>>7, rem = e&127, l = rem>>3, t4 = (rem&7)*4;
            *(float4*)&Ssm[(h*16+l)*32+t4] =
                *(const float4*)(g_S + (((size_t)b*HH+h)*LL + l0+l)*LL + t0 + t4);
        }
        __syncthreads();
#pragma unroll
        for (int l=0;l<16;l++) {
            float z = 0.f;
#pragma unroll
            for (int h=0;h<8;h++) z += Rr[h]*Ssm[(h*16+l)*32 + lane];
            size_t gi = (((size_t)b*HH+i)*LL + l0+l)*LL + t0 + lane;
            if (!(adj[gi] > 0.f)) z = NEGB;
            Ab[gi] = z;
            float mo = m16[l];
            if (z > mo) { s16[l] = s16[l]*__expf(mo - z) + 1.f; m16[l] = z; }
            else s16[l] += __expf(z - mo);
        }
    }
#pragma unroll
    for (int l=0;l<16;l++) {
        float m = m16[l], s = s16[l];
#pragma unroll
        for (int o=16;o;o>>=1) {
            float mo = __shfl_xor_sync(0xffffffffu, m, o);
            float so = __shfl_xor_sync(0xffffffffu, s, o);
            float mn = fmaxf(m, mo);
            s = s*__expf(m-mn) + so*__expf(mo-mn);
            m = mn;
        }
        if (lane == 0) {
            g_rm[((size_t)b*HH+i)*LL + l0+l] = m;
            g_rs[((size_t)b*HH+i)*LL + l0+l] = s;
        }
    }
}

/* K6: A = exp(z-m)/s in place; colsum += sum_l exp(A); v = A @ xv. */
__global__ void k6_norm_v(float* __restrict__ Ab) {
    __shared__ float Ps[32][36], xs[32][36], csum[LL];
    __shared__ float rm[32], ri[32];
    int tid = threadIdx.x, bh = blockIdx.y;
    int l0 = blockIdx.x * 32;
    if (tid < 32) {
        rm[tid] = g_rm[(size_t)bh*LL + l0+tid];
        ri[tid] = 1.f / g_rs[(size_t)bh*LL + l0+tid];
    }
#pragma unroll
    for (int i=0;i<4;i++) csum[tid+i*256] = 0.f;
    int lq = tid>>3, dg = tid&7;
    float4 acc = make_float4(0.f,0.f,0.f,0.f);
    __syncthreads();
    for (int t0=0; t0<LL; t0+=32) {
        {
            int l = tid>>3, t4 = (tid&7)*4;
            float4 z = *(const float4*)(Ab + ((size_t)bh*LL + l0+l)*LL + t0 + t4);
            float m = rm[l], s = ri[l];
            float4 p;
            p.x = __expf(z.x-m)*s; p.y = __expf(z.y-m)*s;
            p.z = __expf(z.z-m)*s; p.w = __expf(z.w-m)*s;
            *(float4*)&Ps[l][t4] = p;
            *(float4*)(Ab + ((size_t)bh*LL + l0+l)*LL + t0 + t4) = p;
            *(float4*)&xs[l][t4] = *(const float4*)(g_xv + ((size_t)bh*LL + t0+l)*DH + t4);
        }
        __syncthreads();
        {
            int w = tid>>5, t = tid&31;
            float s = __expf(Ps[w*4][t]) + __expf(Ps[w*4+1][t])
                    + __expf(Ps[w*4+2][t]) + __expf(Ps[w*4+3][t]);
            atomicAdd(&csum[t0+t], s);
        }
#pragma unroll
        for (int tt=0; tt<32; tt++) {
            float p = Ps[lq][tt];
            float4 x4 = *(const float4*)&xs[tt][dg*4];
            acc.x += p*x4.x; acc.y += p*x4.y; acc.z += p*x4.z; acc.w += p*x4.w;
        }
        __syncthreads();
    }
    int b = bh>>3, h = bh&7;
    *(float4*)(g_v + (size_t)(b*LL + l0+lq)*DIMF + h*DH + dg*4) = acc;
#pragma unroll
    for (int i=0;i<4;i++)
        atomicAdd(&g_cs[(size_t)bh*LL + tid + i*256], csum[tid+i*256]);
}

/* K7: Ar[t,l] = exp(A[l,t])/colsum[t] (transposed, coalesced write); vr = Ar @ rv. */
__global__ void k7_ar_vr(const float* __restrict__ Ab, float* __restrict__ Ar) {
    __shared__ float Es[32][36], rs_[32][36], ci[32];
    int tid = threadIdx.x, bh = blockIdx.y;
    int t0 = blockIdx.x * 32;
    if (tid < 32) ci[tid] = 1.f / g_cs[(size_t)bh*LL + t0 + tid];
    int tq = tid>>3, dg = tid&7;
    float4 acc = make_float4(0.f,0.f,0.f,0.f);
    __syncthreads();
    for (int l0=0; l0<LL; l0+=32) {
        {
            int l = tid>>3, t4 = (tid&7)*4;
            float4 a = *(const float4*)(Ab + ((size_t)bh*LL + l0+l)*LL + t0 + t4);
            Es[t4  ][l] = __expf(a.x)*ci[t4];
            Es[t4+1][l] = __expf(a.y)*ci[t4+1];
            Es[t4+2][l] = __expf(a.z)*ci[t4+2];
            Es[t4+3][l] = __expf(a.w)*ci[t4+3];
            *(float4*)&rs_[l][t4] = *(const float4*)(g_rv + ((size_t)bh*LL + l0+l)*DH + t4);
        }
        __syncthreads();
        {
            int t = tid>>3, l4 = (tid&7)*4;
            *(float4*)(Ar + ((size_t)bh*LL + t0+t)*LL + l0 + l4) = *(float4*)&Es[t][l4];
        }
#pragma unroll
        for (int ll=0; ll<32; ll++) {
            float e = Es[tq][ll];
            float4 r4 = *(const float4*)&rs_[ll][dg*4];
            acc.x += e*r4.x; acc.y += e*r4.y; acc.z += e*r4.z; acc.w += e*r4.w;
        }
        __syncthreads();
    }
    int b = bh>>3, h = bh&7;
    *(float4*)(g_vr + (size_t)(b*LL + t0+tq)*DIMF + h*DH + dg*4) = acc;
}

/* K8: out = gelu(v) @ Wp (z=0), out_resize = gelu(vr) @ Wp (z=1). 64x64 tiles. */
__global__ void k8_out(const float* __restrict__ Wp, float* __restrict__ out,
                       float* __restrict__ outr) {
    __shared__ float Vs[64][36], Ws[32][68];
    int tid = threadIdx.x;
    const float* V = blockIdx.z ? g_vr : g_v;
    float* O = blockIdx.z ? outr : out;
    int r0 = blockIdx.x*64, n0 = blockIdx.y*64;
    int rg = tid>>4, ng = tid&15;
    float4 acc[4];
#pragma unroll
    for (int i=0;i<4;i++) acc[i] = make_float4(0.f,0.f,0.f,0.f);
    for (int k0=0; k0<DIMF; k0+=32) {
#pragma unroll
        for (int it=0; it<2; it++) {
            int e = tid + it*256;
            int r = e>>3, k4 = (e&7)*4;
            float4 v = *(const float4*)(V + (size_t)(r0+r)*DIMF + k0 + k4);
            float* pv = (float*)&v;
#pragma unroll
            for (int j=0;j<4;j++){ float xx = pv[j]; pv[j] = 0.5f*xx*(1.f+erff(xx*0.70710678f)); }
            *(float4*)&Vs[r][k4] = v;
            int kk = e>>4, n4 = (e&15)*4;
            *(float4*)&Ws[kk][n4] = *(const float4*)(Wp + (size_t)(k0+kk)*DIMF + n0 + n4);
        }
        __syncthreads();
#pragma unroll
        for (int k=0;k<32;k++) {
            float4 w4 = *(const float4*)&Ws[k][ng*4];
#pragma unroll
            for (int i=0;i<4;i++) {
                float vv = Vs[rg+16*i][k];
                acc[i].x += vv*w4.x; acc[i].y += vv*w4.y;
                acc[i].z += vv*w4.z; acc[i].w += vv*w4.w;
            }
        }
        __syncthreads();
    }
#pragma unroll
    for (int i=0;i<4;i++)
        *(float4*)(O + (size_t)(r0+rg+16*i)*DIMF + n0 + ng*4) = acc[i];
}

extern "C" void kernel_launch(void* const* d_in, const int* in_sizes, int n_in,
                              void* d_out, int out_size) {
    const float* x    = (const float*)d_in[0];
    const float* rx   = (const float*)d_in[1];
    const float* adj  = (const float*)d_in[2];
    const float* adjr = (const float*)d_in[3];
    const float* Wq   = (const float*)d_in[4];
    const float* Wk   = (const float*)d_in[5];
    const float* Wv   = (const float*)d_in[6];
    const float* R    = (const float*)d_in[7];
    const float* Wp   = (const float*)d_in[8];
    float* out  = (float*)d_out;              /* [4,1024,256]    */
    float* outr = out + 1048576;              /* [4,1024,256]    */
    float* Ab   = out + 2097152;              /* A  [4,8,1024,1024] */
    float* Arb  = Ab + 33554432;              /* Ar [4,8,1024,1024] */
    k1_proj<<<4096, 256>>>(x, rx, Wq, Wk, Wv);
    k2_agg<<<dim3(8,32,2), 256>>>(adj, adjr);
    k3_logits<<<dim3(256,32), 256>>>();
    k4_mix<<<dim3(64,4), 256>>>(adj, R, Ab);
    k6_norm_v<<<dim3(32,32), 256>>>(Ab);
    k7_ar_vr<<<dim3(32,32), 256>>>(Ab, Arb);
    k8_out<<<dim3(64,4,2), 256>>>(Wp, out, outr);
}

// round 3
// speedup vs baseline: 1.3091x; 1.3091x over previous
#include <cuda_runtime.h>
#include <math.h>

#define BB 4
#define HH 8
#define LL 1024
#define DIMF 256
#define DH 32
#define SCL 0.0625f
#define NEGB (-1e30f)

__device__ float g_xq[BB*HH*LL*DH];
__device__ float g_rk[BB*HH*LL*DH];
__device__ float g_xv[BB*HH*LL*DH];
__device__ float g_rv[BB*HH*LL*DH];
__device__ float g_q [BB*HH*LL*DH];
__device__ float g_k [BB*HH*LL*DH];
__device__ float g_rm2[2*BB*HH*LL];
__device__ float g_rs2[2*BB*HH*LL];
__device__ float g_rm[BB*HH*LL];
__device__ float g_rs[BB*HH*LL];
__device__ float g_cs[BB*HH*LL];
__device__ float g_v [BB*LL*DIMF];
__device__ float g_vr[BB*LL*DIMF];

/* K1: per-head projections xq=xh@Wq, xv=xh@Wv, rk=rxh@Wk, rv=rxh@Wv; zero g_cs */
__global__ void k1_proj(const float* __restrict__ x, const float* __restrict__ rx,
                        const float* __restrict__ Wq, const float* __restrict__ Wk,
                        const float* __restrict__ Wv) {
    __shared__ float wq[DH*DH], wk[DH*DH], wv[DH*DH];
    __shared__ float xr[DIMF], rr[DIMF];
    int tid = threadIdx.x, bl = blockIdx.x;
    if (bl < 128) g_cs[bl*256 + tid] = 0.f;
    for (int i = tid; i < DH*DH; i += 256) { wq[i]=Wq[i]; wk[i]=Wk[i]; wv[i]=Wv[i]; }
    xr[tid] = x[(size_t)bl*DIMF + tid];
    rr[tid] = rx[(size_t)bl*DIMF + tid];
    __syncthreads();
    int h = tid>>5, d = tid&31;
    float aq=0.f, av=0.f, ak=0.f, ar=0.f;
#pragma unroll
    for (int j=0;j<DH;j++) {
        float xv_ = xr[h*DH+j], rv_ = rr[h*DH+j];
        aq += xv_*wq[j*DH+d]; av += xv_*wv[j*DH+d];
        ak += rv_*wk[j*DH+d]; ar += rv_*wv[j*DH+d];
    }
    int b = bl>>10, l = bl&1023;
    size_t o = (((size_t)b*HH + h)*LL + l)*DH + d;
    g_xq[o]=aq; g_xv[o]=av; g_rk[o]=ak; g_rv[o]=ar;
}

/* K2: q = adj @ xq (z=0), k = adj_resize @ rk (z=1). 128x32 tile, 4x4 regs. */
__global__ void k2_agg(const float* __restrict__ adj, const float* __restrict__ adjr) {
    __shared__ float aS[128][36];
    __shared__ float xS[32][36];
    int tid = threadIdx.x, bh = blockIdx.y;
    int r0 = blockIdx.x * 128;
    const float* A = blockIdx.z ? adjr : adj;
    const float* X = blockIdx.z ? g_rk : g_xq;
    float*       O = blockIdx.z ? g_k  : g_q;
    int rg = tid>>3, cg = tid&7;
    float4 acc[4];
#pragma unroll
    for (int i=0;i<4;i++) acc[i] = make_float4(0.f,0.f,0.f,0.f);
    const float* Ab = A + (size_t)bh*LL*LL;
    for (int t0=0; t0<LL; t0+=32) {
#pragma unroll
        for (int i=0;i<4;i++) {
            int e = tid + i*256, r = e>>3, c4 = (e&7)*4;
            *(float4*)&aS[r][c4] = *(const float4*)(Ab + (size_t)(r0+r)*LL + t0 + c4);
        }
        {
            int tt = tid>>3, d4 = (tid&7)*4;
            *(float4*)&xS[tt][d4] = *(const float4*)(X + ((size_t)bh*LL + t0+tt)*DH + d4);
        }
        __syncthreads();
#pragma unroll
        for (int tq=0; tq<8; tq++) {
            float4 a4[4], x4[4];
#pragma unroll
            for (int i=0;i<4;i++) a4[i] = *(const float4*)&aS[rg+32*i][tq*4];
#pragma unroll
            for (int m=0;m<4;m++) x4[m] = *(const float4*)&xS[tq*4+m][cg*4];
#pragma unroll
            for (int i=0;i<4;i++) {
                acc[i].x += a4[i].x*x4[0].x + a4[i].y*x4[1].x + a4[i].z*x4[2].x + a4[i].w*x4[3].x;
                acc[i].y += a4[i].x*x4[0].y + a4[i].y*x4[1].y + a4[i].z*x4[2].y + a4[i].w*x4[3].y;
                acc[i].z += a4[i].x*x4[0].z + a4[i].y*x4[1].z + a4[i].z*x4[2].z + a4[i].w*x4[3].z;
                acc[i].w += a4[i].x*x4[0].w + a4[i].y*x4[1].w + a4[i].z*x4[2].w + a4[i].w*x4[3].w;
            }
        }
        __syncthreads();
    }
#pragma unroll
    for (int i=0;i<4;i++)
        *(float4*)(O + ((size_t)bh*LL + r0+rg+32*i)*DH + cg*4) = acc[i];
}

/* K34: fused logits + leaky + R-mix + mask + online row stats.
   block: 256 thr, 16 l-rows, all 8 heads; blockIdx.z = t-half (512 cols each).
   dynamic smem: qs[8][16][36] | ks[8][32][36] | Ss[8][16][36]  (73728 B). */
__global__ void k34_fused(const float* __restrict__ adj, const float* __restrict__ R,
                          float* __restrict__ Ab) {
    extern __shared__ float sm[];
    float* qs = sm;            /* 4608 */
    float* ks = sm + 4608;     /* 9216 */
    float* Ss = sm + 13824;    /* 4608 */
    int tid = threadIdx.x, b = blockIdx.y, l0 = blockIdx.x*16;
    int w = tid>>5, lane = tid&31;
    int lg = lane>>3, tg = lane&7;
    float Rr[8];
#pragma unroll
    for (int h=0;h<8;h++) Rr[h] = R[w*8+h];
#pragma unroll
    for (int i=0;i<4;i++) {
        int e = tid + i*256;
        int h = e>>7, rem = e&127, l = rem>>3, d4 = (rem&7)*4;
        *(float4*)&qs[(h*16+l)*36+d4] =
            *(const float4*)(g_q + (((size_t)b*HH+h)*LL + l0+l)*DH + d4);
    }
    float m16[16], s16[16];
#pragma unroll
    for (int l=0;l<16;l++){ m16[l]=NEGB; s16[l]=0.f; }
    int tbeg = blockIdx.z*512, tend = tbeg+512;
    for (int t0=tbeg; t0<tend; t0+=32) {
        __syncthreads();
#pragma unroll
        for (int i=0;i<8;i++) {
            int e = tid + i*256;
            int h = e>>8, rem = e&255, tt = rem>>3, d4 = (rem&7)*4;
            *(float4*)&ks[(h*32+tt)*36+d4] =
                *(const float4*)(g_k + (((size_t)b*HH+h)*LL + t0+tt)*DH + d4);
        }
        __syncthreads();
        /* phase1: warp w computes S tile for input head h=w (16x32, 4x4/thread) */
        {
            float s[4][4];
#pragma unroll
            for (int i=0;i<4;i++)
#pragma unroll
                for (int j=0;j<4;j++) s[i][j]=0.f;
#pragma unroll
            for (int dq=0; dq<8; dq++) {
                float4 q4[4], k4[4];
#pragma unroll
                for (int i=0;i<4;i++) q4[i] = *(const float4*)&qs[(w*16+lg+4*i)*36+dq*4];
#pragma unroll
                for (int j=0;j<4;j++) k4[j] = *(const float4*)&ks[(w*32+tg+8*j)*36+dq*4];
#pragma unroll
                for (int i=0;i<4;i++)
#pragma unroll
                    for (int j=0;j<4;j++)
                        s[i][j] += q4[i].x*k4[j].x + q4[i].y*k4[j].y
                                 + q4[i].z*k4[j].z + q4[i].w*k4[j].w;
            }
#pragma unroll
            for (int i=0;i<4;i++)
#pragma unroll
                for (int j=0;j<4;j++) {
                    float v = s[i][j]*SCL;
                    Ss[(w*16+lg+4*i)*36+tg+8*j] = v>0.f ? v : 0.01f*v;
                }
        }
        __syncthreads();
        /* phase2: warp w = output head, lane = t; mix, mask, write, stats */
#pragma unroll
        for (int l=0;l<16;l++) {
            float z = 0.f;
#pragma unroll
            for (int h=0;h<8;h++) z += Rr[h]*Ss[(h*16+l)*36 + lane];
            size_t gi = (((size_t)b*HH+w)*LL + l0+l)*LL + t0 + lane;
            if (!(adj[gi] > 0.f)) z = NEGB;
            Ab[gi] = z;
            float mo = m16[l];
            if (z > mo) { s16[l] = s16[l]*__expf(mo - z) + 1.f; m16[l] = z; }
            else s16[l] += __expf(z - mo);
        }
    }
#pragma unroll
    for (int l=0;l<16;l++) {
        float m = m16[l], s = s16[l];
#pragma unroll
        for (int o=16;o;o>>=1) {
            float mo = __shfl_xor_sync(0xffffffffu, m, o);
            float so = __shfl_xor_sync(0xffffffffu, s, o);
            float mn = fmaxf(m, mo);
            s = s*__expf(m-mn) + so*__expf(mo-mn);
            m = mn;
        }
        if (lane == 0) {
            size_t ridx = ((size_t)b*HH+w)*LL + l0+l;
            g_rm2[(size_t)blockIdx.z*32768 + ridx] = m;
            g_rs2[(size_t)blockIdx.z*32768 + ridx] = s;
        }
    }
}

/* K5m: merge the two t-half softmax stats per row. */
__global__ void k5_merge() {
    int i = blockIdx.x*256 + threadIdx.x;
    float m1 = g_rm2[i], m2 = g_rm2[32768+i];
    float s1 = g_rs2[i], s2 = g_rs2[32768+i];
    float m = fmaxf(m1, m2);
    float s = s1*__expf(m1-m) + s2*__expf(m2-m);
    g_rm[i] = m; g_rs[i] = s;
}

/* K6: A = exp(z-m)/s in place; colsum += sum_l exp(A); v = A @ xv. */
__global__ void k6_norm_v(float* __restrict__ Ab) {
    __shared__ float Ps[32][36], xs[32][36], csum[LL];
    __shared__ float rm[32], ri[32];
    int tid = threadIdx.x, bh = blockIdx.y;
    int l0 = blockIdx.x * 32;
    if (tid < 32) {
        rm[tid] = g_rm[(size_t)bh*LL + l0+tid];
        ri[tid] = 1.f / g_rs[(size_t)bh*LL + l0+tid];
    }
#pragma unroll
    for (int i=0;i<4;i++) csum[tid+i*256] = 0.f;
    int lq = tid>>3, dg = tid&7;
    float4 acc = make_float4(0.f,0.f,0.f,0.f);
    __syncthreads();
    for (int t0=0; t0<LL; t0+=32) {
        {
            int l = tid>>3, t4 = (tid&7)*4;
            float4 z = *(const float4*)(Ab + ((size_t)bh*LL + l0+l)*LL + t0 + t4);
            float m = rm[l], s = ri[l];
            float4 p;
            p.x = __expf(z.x-m)*s; p.y = __expf(z.y-m)*s;
            p.z = __expf(z.z-m)*s; p.w = __expf(z.w-m)*s;
            *(float4*)&Ps[l][t4] = p;
            *(float4*)(Ab + ((size_t)bh*LL + l0+l)*LL + t0 + t4) = p;
            *(float4*)&xs[l][t4] = *(const float4*)(g_xv + ((size_t)bh*LL + t0+l)*DH + t4);
        }
        __syncthreads();
        {
            int w = tid>>5, t = tid&31;
            float s = __expf(Ps[w*4][t]) + __expf(Ps[w*4+1][t])
                    + __expf(Ps[w*4+2][t]) + __expf(Ps[w*4+3][t]);
            atomicAdd(&csum[t0+t], s);
        }
#pragma unroll
        for (int tt=0; tt<32; tt++) {
            float p = Ps[lq][tt];
            float4 x4 = *(const float4*)&xs[tt][dg*4];
            acc.x += p*x4.x; acc.y += p*x4.y; acc.z += p*x4.z; acc.w += p*x4.w;
        }
        __syncthreads();
    }
    int b = bh>>3, h = bh&7;
    *(float4*)(g_v + (size_t)(b*LL + l0+lq)*DIMF + h*DH + dg*4) = acc;
#pragma unroll
    for (int i=0;i<4;i++)
        atomicAdd(&g_cs[(size_t)bh*LL + tid + i*256], csum[tid+i*256]);
}

/* K7: Ar[t,l] = exp(A[l,t])/colsum[t] (transposed, coalesced write); vr = Ar @ rv. */
__global__ void k7_ar_vr(const float* __restrict__ Ab, float* __restrict__ Ar) {
    __shared__ float Es[32][36], rs_[32][36], ci[32];
    int tid = threadIdx.x, bh = blockIdx.y;
    int t0 = blockIdx.x * 32;
    if (tid < 32) ci[tid] = 1.f / g_cs[(size_t)bh*LL + t0 + tid];
    int tq = tid>>3, dg = tid&7;
    float4 acc = make_float4(0.f,0.f,0.f,0.f);
    __syncthreads();
    for (int l0=0; l0<LL; l0+=32) {
        {
            int l = tid>>3, t4 = (tid&7)*4;
            float4 a = *(const float4*)(Ab + ((size_t)bh*LL + l0+l)*LL + t0 + t4);
            Es[t4  ][l] = __expf(a.x)*ci[t4];
            Es[t4+1][l] = __expf(a.y)*ci[t4+1];
            Es[t4+2][l] = __expf(a.z)*ci[t4+2];
            Es[t4+3][l] = __expf(a.w)*ci[t4+3];
            *(float4*)&rs_[l][t4] = *(const float4*)(g_rv + ((size_t)bh*LL + l0+l)*DH + t4);
        }
        __syncthreads();
        {
            int t = tid>>3, l4 = (tid&7)*4;
            *(float4*)(Ar + ((size_t)bh*LL + t0+t)*LL + l0 + l4) = *(float4*)&Es[t][l4];
        }
#pragma unroll
        for (int ll=0; ll<32; ll++) {
            float e = Es[tq][ll];
            float4 r4 = *(const float4*)&rs_[ll][dg*4];
            acc.x += e*r4.x; acc.y += e*r4.y; acc.z += e*r4.z; acc.w += e*r4.w;
        }
        __syncthreads();
    }
    int b = bh>>3, h = bh&7;
    *(float4*)(g_vr + (size_t)(b*LL + t0+tq)*DIMF + h*DH + dg*4) = acc;
}

/* K8: out = gelu(v) @ Wp (z=0), out_resize = gelu(vr) @ Wp (z=1). 64x64 tiles. */
__global__ void k8_out(const float* __restrict__ Wp, float* __restrict__ out,
                       float* __restrict__ outr) {
    __shared__ float Vs[64][36], Ws[32][68];
    int tid = threadIdx.x;
    const float* V = blockIdx.z ? g_vr : g_v;
    float* O = blockIdx.z ? outr : out;
    int r0 = blockIdx.x*64, n0 = blockIdx.y*64;
    int rg = tid>>4, ng = tid&15;
    float4 acc[4];
#pragma unroll
    for (int i=0;i<4;i++) acc[i] = make_float4(0.f,0.f,0.f,0.f);
    for (int k0=0; k0<DIMF; k0+=32) {
#pragma unroll
        for (int it=0; it<2; it++) {
            int e = tid + it*256;
            int r = e>>3, k4 = (e&7)*4;
            float4 v = *(const float4*)(V + (size_t)(r0+r)*DIMF + k0 + k4);
            float* pv = (float*)&v;
#pragma unroll
            for (int j=0;j<4;j++){ float xx = pv[j]; pv[j] = 0.5f*xx*(1.f+erff(xx*0.70710678f)); }
            *(float4*)&Vs[r][k4] = v;
            int kk = e>>4, n4 = (e&15)*4;
            *(float4*)&Ws[kk][n4] = *(const float4*)(Wp + (size_t)(k0+kk)*DIMF + n0 + n4);
        }
        __syncthreads();
#pragma unroll
        for (int k=0;k<32;k++) {
            float4 w4 = *(const float4*)&Ws[k][ng*4];
#pragma unroll
            for (int i=0;i<4;i++) {
                float vv = Vs[rg+16*i][k];
                acc[i].x += vv*w4.x; acc[i].y += vv*w4.y;
                acc[i].z += vv*w4.z; acc[i].w += vv*w4.w;
            }
        }
        __syncthreads();
    }
#pragma unroll
    for (int i=0;i<4;i++)
        *(float4*)(O + (size_t)(r0+rg+16*i)*DIMF + n0 + ng*4) = acc[i];
}

extern "C" void kernel_launch(void* const* d_in, const int* in_sizes, int n_in,
                              void* d_out, int out_size) {
    const float* x    = (const float*)d_in[0];
    const float* rx   = (const float*)d_in[1];
    const float* adj  = (const float*)d_in[2];
    const float* adjr = (const float*)d_in[3];
    const float* Wq   = (const float*)d_in[4];
    const float* Wk   = (const float*)d_in[5];
    const float* Wv   = (const float*)d_in[6];
    const float* R    = (const float*)d_in[7];
    const float* Wp   = (const float*)d_in[8];
    float* out  = (float*)d_out;              /* [4,1024,256]    */
    float* outr = out + 1048576;              /* [4,1024,256]    */
    float* Ab   = out + 2097152;              /* A  [4,8,1024,1024] */
    float* Arb  = Ab + 33554432;              /* Ar [4,8,1024,1024] */
    static int smset = 0;
    if (!smset) {
        cudaFuncSetAttribute(k34_fused, cudaFuncAttributeMaxDynamicSharedMemorySize, 73728);
        smset = 1;
    }
    k1_proj<<<4096, 256>>>(x, rx, Wq, Wk, Wv);
    k2_agg<<<dim3(8,32,2), 256>>>(adj, adjr);
    k34_fused<<<dim3(64,4,2), 256, 73728>>>(adj, R, Ab);
    k5_merge<<<128, 256>>>();
    k6_norm_v<<<dim3(32,32), 256>>>(Ab);
    k7_ar_vr<<<dim3(32,32), 256>>>(Ab, Arb);
    k8_out<<<dim3(64,4,2), 256>>>(Wp, out, outr);
}

// round 4
// speedup vs baseline: 1.3748x; 1.0502x over previous
#include <cuda_runtime.h>
#include <math.h>

#define BB 4
#define HH 8
#define LL 1024
#define DIMF 256
#define DH 32
#define SCL 0.0625f
#define NEGB (-1e30f)

__device__ float g_xq[BB*HH*LL*DH];
__device__ float g_rk[BB*HH*LL*DH];
__device__ float g_xv[BB*HH*LL*DH];
__device__ float g_rv[BB*HH*LL*DH];
__device__ float g_q [BB*HH*LL*DH];
__device__ float g_k [BB*HH*LL*DH];
__device__ float g_rm2[2*BB*HH*LL];
__device__ float g_rs2[2*BB*HH*LL];
__device__ float g_rm[BB*HH*LL];
__device__ float g_rs[BB*HH*LL];
__device__ float g_cs[BB*HH*LL];
__device__ float g_v [BB*LL*DIMF];
__device__ float g_vr[BB*LL*DIMF];

/* K1: per-head projections xq=xh@Wq, xv=xh@Wv, rk=rxh@Wk, rv=rxh@Wv; zero g_cs */
__global__ void k1_proj(const float* __restrict__ x, const float* __restrict__ rx,
                        const float* __restrict__ Wq, const float* __restrict__ Wk,
                        const float* __restrict__ Wv) {
    __shared__ float wq[DH*DH], wk[DH*DH], wv[DH*DH];
    __shared__ float xr[DIMF], rr[DIMF];
    int tid = threadIdx.x, bl = blockIdx.x;
    if (bl < 128) g_cs[bl*256 + tid] = 0.f;
    for (int i = tid; i < DH*DH; i += 256) { wq[i]=Wq[i]; wk[i]=Wk[i]; wv[i]=Wv[i]; }
    xr[tid] = x[(size_t)bl*DIMF + tid];
    rr[tid] = rx[(size_t)bl*DIMF + tid];
    __syncthreads();
    int h = tid>>5, d = tid&31;
    float aq=0.f, av=0.f, ak=0.f, ar=0.f;
#pragma unroll
    for (int j=0;j<DH;j++) {
        float xv_ = xr[h*DH+j], rv_ = rr[h*DH+j];
        aq += xv_*wq[j*DH+d]; av += xv_*wv[j*DH+d];
        ak += rv_*wk[j*DH+d]; ar += rv_*wv[j*DH+d];
    }
    int b = bl>>10, l = bl&1023;
    size_t o = (((size_t)b*HH + h)*LL + l)*DH + d;
    g_xq[o]=aq; g_xv[o]=av; g_rk[o]=ak; g_rv[o]=ar;
}

/* K2s: sparse aggregation. adj entries are exactly {0,1}, ~10% dense,
   so q[l] = sum of xq rows where adj[l,t]==1. One warp per row (d = lane),
   ballot over 32-entry adj chunks, one coalesced 128B add per set bit. */
__global__ void k2s_agg(const float* __restrict__ adj, const float* __restrict__ adjr) {
    int tid = threadIdx.x, w = tid>>5, lane = tid&31;
    int bh = blockIdx.y;
    const float* A = blockIdx.z ? adjr : adj;
    const float* X = blockIdx.z ? g_rk : g_xq;
    float*       O = blockIdx.z ? g_k  : g_q;
    const float* Ab = A + (size_t)bh*LL*LL;
    const float* Xb = X + (size_t)bh*LL*DH;
    float*       Ob = O + (size_t)bh*LL*DH;
    int lbase = blockIdx.x*32 + w*4;
#pragma unroll
    for (int r=0; r<4; r++) {
        int row = lbase + r;
        const float* arow = Ab + (size_t)row*LL;
        float acc = 0.f;
        for (int t0=0; t0<LL; t0+=32) {
            float av = arow[t0+lane];
            unsigned mask = __ballot_sync(0xffffffffu, av > 0.f);
            while (mask) {
                int b = __ffs(mask)-1; mask &= mask-1;
                acc += Xb[(size_t)(t0+b)*DH + lane];
            }
        }
        Ob[(size_t)row*DH + lane] = acc;
    }
}

/* K34: fused logits + leaky + R-mix + mask + online row stats.
   block: 256 thr, 16 l-rows, all 8 heads; blockIdx.z = t-half (512 cols each).
   dynamic smem: qs[8][16][36] | ks[8][32][36] | Ss[8][16][36]  (73728 B). */
__global__ void k34_fused(const float* __restrict__ adj, const float* __restrict__ R,
                          float* __restrict__ Ab) {
    extern __shared__ float sm[];
    float* qs = sm;            /* 4608 */
    float* ks = sm + 4608;     /* 9216 */
    float* Ss = sm + 13824;    /* 4608 */
    int tid = threadIdx.x, b = blockIdx.y, l0 = blockIdx.x*16;
    int w = tid>>5, lane = tid&31;
    int lg = lane>>3, tg = lane&7;
    float Rr[8];
#pragma unroll
    for (int h=0;h<8;h++) Rr[h] = R[w*8+h];
#pragma unroll
    for (int i=0;i<4;i++) {
        int e = tid + i*256;
        int h = e>>7, rem = e&127, l = rem>>3, d4 = (rem&7)*4;
        *(float4*)&qs[(h*16+l)*36+d4] =
            *(const float4*)(g_q + (((size_t)b*HH+h)*LL + l0+l)*DH + d4);
    }
    float m16[16], s16[16];
#pragma unroll
    for (int l=0;l<16;l++){ m16[l]=NEGB; s16[l]=0.f; }
    int tbeg = blockIdx.z*512, tend = tbeg+512;
    for (int t0=tbeg; t0<tend; t0+=32) {
        __syncthreads();
#pragma unroll
        for (int i=0;i<8;i++) {
            int e = tid + i*256;
            int h = e>>8, rem = e&255, tt = rem>>3, d4 = (rem&7)*4;
            *(float4*)&ks[(h*32+tt)*36+d4] =
                *(const float4*)(g_k + (((size_t)b*HH+h)*LL + t0+tt)*DH + d4);
        }
        __syncthreads();
        {
            float s[4][4];
#pragma unroll
            for (int i=0;i<4;i++)
#pragma unroll
                for (int j=0;j<4;j++) s[i][j]=0.f;
#pragma unroll
            for (int dq=0; dq<8; dq++) {
                float4 q4[4], k4[4];
#pragma unroll
                for (int i=0;i<4;i++) q4[i] = *(const float4*)&qs[(w*16+lg+4*i)*36+dq*4];
#pragma unroll
                for (int j=0;j<4;j++) k4[j] = *(const float4*)&ks[(w*32+tg+8*j)*36+dq*4];
#pragma unroll
                for (int i=0;i<4;i++)
#pragma unroll
                    for (int j=0;j<4;j++)
                        s[i][j] += q4[i].x*k4[j].x + q4[i].y*k4[j].y
                                 + q4[i].z*k4[j].z + q4[i].w*k4[j].w;
            }
#pragma unroll
            for (int i=0;i<4;i++)
#pragma unroll
                for (int j=0;j<4;j++) {
                    float v = s[i][j]*SCL;
                    Ss[(w*16+lg+4*i)*36+tg+8*j] = v>0.f ? v : 0.01f*v;
                }
        }
        __syncthreads();
#pragma unroll
        for (int l=0;l<16;l++) {
            float z = 0.f;
#pragma unroll
            for (int h=0;h<8;h++) z += Rr[h]*Ss[(h*16+l)*36 + lane];
            size_t gi = (((size_t)b*HH+w)*LL + l0+l)*LL + t0 + lane;
            if (!(adj[gi] > 0.f)) z = NEGB;
            Ab[gi] = z;
            float mo = m16[l];
            if (z > mo) { s16[l] = s16[l]*__expf(mo - z) + 1.f; m16[l] = z; }
            else s16[l] += __expf(z - mo);
        }
    }
#pragma unroll
    for (int l=0;l<16;l++) {
        float m = m16[l], s = s16[l];
#pragma unroll
        for (int o=16;o;o>>=1) {
            float mo = __shfl_xor_sync(0xffffffffu, m, o);
            float so = __shfl_xor_sync(0xffffffffu, s, o);
            float mn = fmaxf(m, mo);
            s = s*__expf(m-mn) + so*__expf(mo-mn);
            m = mn;
        }
        if (lane == 0) {
            size_t ridx = ((size_t)b*HH+w)*LL + l0+l;
            g_rm2[(size_t)blockIdx.z*32768 + ridx] = m;
            g_rs2[(size_t)blockIdx.z*32768 + ridx] = s;
        }
    }
}

/* K5m: merge the two t-half softmax stats per row. */
__global__ void k5_merge() {
    int i = blockIdx.x*256 + threadIdx.x;
    float m1 = g_rm2[i], m2 = g_rm2[32768+i];
    float s1 = g_rs2[i], s2 = g_rs2[32768+i];
    float m = fmaxf(m1, m2);
    float s = s1*__expf(m1-m) + s2*__expf(m2-m);
    g_rm[i] = m; g_rs[i] = s;
}

/* K6: A = exp(z-m)/s in place; colsum += sum_l exp(A); v = A @ xv.
   128 threads, 64 l-rows/block, 4 rows x 4 cols per thread. */
__global__ void k6_norm_v(float* __restrict__ Ab) {
    __shared__ float Ps[64][36], xs[32][36], csum[LL];
    __shared__ float rm[64], ri[64];
    int tid = threadIdx.x, bh = blockIdx.y;
    int l0 = blockIdx.x * 64;
    if (tid < 64) {
        rm[tid] = g_rm[(size_t)bh*LL + l0+tid];
        ri[tid] = 1.f / g_rs[(size_t)bh*LL + l0+tid];
    }
#pragma unroll
    for (int i=0;i<8;i++) csum[tid+i*128] = 0.f;
    int lq = tid>>3, dg = tid&7;
    float4 acc[4];
#pragma unroll
    for (int i=0;i<4;i++) acc[i] = make_float4(0.f,0.f,0.f,0.f);
    __syncthreads();
    for (int t0=0; t0<LL; t0+=32) {
#pragma unroll
        for (int i=0;i<4;i++) {
            int e = tid + i*128, l = e>>3, t4 = (e&7)*4;
            float4 z = *(const float4*)(Ab + ((size_t)bh*LL + l0+l)*LL + t0 + t4);
            float m = rm[l], s = ri[l];
            float4 p;
            p.x = __expf(z.x-m)*s; p.y = __expf(z.y-m)*s;
            p.z = __expf(z.z-m)*s; p.w = __expf(z.w-m)*s;
            *(float4*)&Ps[l][t4] = p;
            *(float4*)(Ab + ((size_t)bh*LL + l0+l)*LL + t0 + t4) = p;
        }
#pragma unroll
        for (int i=0;i<2;i++) {
            int e = tid + i*128, l = e>>3, d4 = (e&7)*4;
            *(float4*)&xs[l][d4] = *(const float4*)(g_xv + ((size_t)bh*LL + t0+l)*DH + d4);
        }
        __syncthreads();
        {
            int w = tid>>5, t = tid&31;
            float s = 0.f;
#pragma unroll
            for (int r=0;r<16;r++) s += __expf(Ps[w*16+r][t]);
            atomicAdd(&csum[t0+t], s);
        }
#pragma unroll
        for (int tt=0; tt<32; tt++) {
            float4 x4 = *(const float4*)&xs[tt][dg*4];
#pragma unroll
            for (int i=0;i<4;i++) {
                float p = Ps[lq+16*i][tt];
                acc[i].x += p*x4.x; acc[i].y += p*x4.y;
                acc[i].z += p*x4.z; acc[i].w += p*x4.w;
            }
        }
        __syncthreads();
    }
    int b = bh>>3, h = bh&7;
#pragma unroll
    for (int i=0;i<4;i++)
        *(float4*)(g_v + (size_t)(b*LL + l0+lq+16*i)*DIMF + h*DH + dg*4) = acc[i];
#pragma unroll
    for (int i=0;i<8;i++)
        atomicAdd(&g_cs[(size_t)bh*LL + tid + i*128], csum[tid+i*128]);
}

/* K7: Ar[t,l] = exp(A[l,t])/colsum[t] (transposed, coalesced write); vr = Ar @ rv.
   128 threads, 64 t-rows/block, 4 rows x 4 cols per thread. */
__global__ void k7_ar_vr(const float* __restrict__ Ab, float* __restrict__ Ar) {
    __shared__ float Es[64][36], rs_[32][36], ci[64];
    int tid = threadIdx.x, bh = blockIdx.y;
    int t0 = blockIdx.x * 64;
    if (tid < 64) ci[tid] = 1.f / g_cs[(size_t)bh*LL + t0 + tid];
    int tq = tid>>3, dg = tid&7;
    float4 acc[4];
#pragma unroll
    for (int i=0;i<4;i++) acc[i] = make_float4(0.f,0.f,0.f,0.f);
    __syncthreads();
    for (int l0=0; l0<LL; l0+=32) {
#pragma unroll
        for (int i=0;i<4;i++) {
            int e = tid + i*128;
            int l = (e>>3)&31, t4 = (e&7)*4 + ((e>>8)<<5);
            float4 a = *(const float4*)(Ab + ((size_t)bh*LL + l0+l)*LL + t0 + t4);
            Es[t4  ][l] = __expf(a.x)*ci[t4];
            Es[t4+1][l] = __expf(a.y)*ci[t4+1];
            Es[t4+2][l] = __expf(a.z)*ci[t4+2];
            Es[t4+3][l] = __expf(a.w)*ci[t4+3];
        }
#pragma unroll
        for (int i=0;i<2;i++) {
            int e = tid + i*128, l = e>>3, d4 = (e&7)*4;
            *(float4*)&rs_[l][d4] = *(const float4*)(g_rv + ((size_t)bh*LL + l0+l)*DH + d4);
        }
        __syncthreads();
#pragma unroll
        for (int i=0;i<4;i++) {
            int e = tid + i*128, t = e>>3, l4 = (e&7)*4;
            *(float4*)(Ar + ((size_t)bh*LL + t0+t)*LL + l0 + l4) = *(float4*)&Es[t][l4];
        }
#pragma unroll
        for (int ll=0; ll<32; ll++) {
            float4 r4 = *(const float4*)&rs_[ll][dg*4];
#pragma unroll
            for (int i=0;i<4;i++) {
                float e_ = Es[tq+16*i][ll];
                acc[i].x += e_*r4.x; acc[i].y += e_*r4.y;
                acc[i].z += e_*r4.z; acc[i].w += e_*r4.w;
            }
        }
        __syncthreads();
    }
    int b = bh>>3, h = bh&7;
#pragma unroll
    for (int i=0;i<4;i++)
        *(float4*)(g_vr + (size_t)(b*LL + t0+tq+16*i)*DIMF + h*DH + dg*4) = acc[i];
}

/* K8: out = gelu(v) @ Wp (z=0), out_resize = gelu(vr) @ Wp (z=1). 64x64 tiles. */
__global__ void k8_out(const float* __restrict__ Wp, float* __restrict__ out,
                       float* __restrict__ outr) {
    __shared__ float Vs[64][36], Ws[32][68];
    int tid = threadIdx.x;
    const float* V = blockIdx.z ? g_vr : g_v;
    float* O = blockIdx.z ? outr : out;
    int r0 = blockIdx.x*64, n0 = blockIdx.y*64;
    int rg = tid>>4, ng = tid&15;
    float4 acc[4];
#pragma unroll
    for (int i=0;i<4;i++) acc[i] = make_float4(0.f,0.f,0.f,0.f);
    for (int k0=0; k0<DIMF; k0+=32) {
#pragma unroll
        for (int it=0; it<2; it++) {
            int e = tid + it*256;
            int r = e>>3, k4 = (e&7)*4;
            float4 v = *(const float4*)(V + (size_t)(r0+r)*DIMF + k0 + k4);
            float* pv = (float*)&v;
#pragma unroll
            for (int j=0;j<4;j++){ float xx = pv[j]; pv[j] = 0.5f*xx*(1.f+erff(xx*0.70710678f)); }
            *(float4*)&Vs[r][k4] = v;
            int kk = e>>4, n4 = (e&15)*4;
            *(float4*)&Ws[kk][n4] = *(const float4*)(Wp + (size_t)(k0+kk)*DIMF + n0 + n4);
        }
        __syncthreads();
#pragma unroll
        for (int k=0;k<32;k++) {
            float4 w4 = *(const float4*)&Ws[k][ng*4];
#pragma unroll
            for (int i=0;i<4;i++) {
                float vv = Vs[rg+16*i][k];
                acc[i].x += vv*w4.x; acc[i].y += vv*w4.y;
                acc[i].z += vv*w4.z; acc[i].w += vv*w4.w;
            }
        }
        __syncthreads();
    }
#pragma unroll
    for (int i=0;i<4;i++)
        *(float4*)(O + (size_t)(r0+rg+16*i)*DIMF + n0 + ng*4) = acc[i];
}

extern "C" void kernel_launch(void* const* d_in, const int* in_sizes, int n_in,
                              void* d_out, int out_size) {
    const float* x    = (const float*)d_in[0];
    const float* rx   = (const float*)d_in[1];
    const float* adj  = (const float*)d_in[2];
    const float* adjr = (const float*)d_in[3];
    const float* Wq   = (const float*)d_in[4];
    const float* Wk   = (const float*)d_in[5];
    const float* Wv   = (const float*)d_in[6];
    const float* R    = (const float*)d_in[7];
    const float* Wp   = (const float*)d_in[8];
    float* out  = (float*)d_out;              /* [4,1024,256]    */
    float* outr = out + 1048576;              /* [4,1024,256]    */
    float* Ab   = out + 2097152;              /* A  [4,8,1024,1024] */
    float* Arb  = Ab + 33554432;              /* Ar [4,8,1024,1024] */
    static int smset = 0;
    if (!smset) {
        cudaFuncSetAttribute(k34_fused, cudaFuncAttributeMaxDynamicSharedMemorySize, 73728);
        smset = 1;
    }
    k1_proj<<<4096, 256>>>(x, rx, Wq, Wk, Wv);
    k2s_agg<<<dim3(32,32,2), 256>>>(adj, adjr);
    k34_fused<<<dim3(64,4,2), 256, 73728>>>(adj, R, Ab);
    k5_merge<<<128, 256>>>();
    k6_norm_v<<<dim3(16,32), 128>>>(Ab);
    k7_ar_vr<<<dim3(16,32), 128>>>(Ab, Arb);
    k8_out<<<dim3(64,4,2), 256>>>(Wp, out, outr);
}